// round 8
// baseline (speedup 1.0000x reference)
#include <cuda_runtime.h>
#include <cstdint>

#define BB 2
#define SQ 1024
#define SK 1024
#define DD 64
#define DV 64
#define QPB 64                 // queries per block
#define KTOT 64                // keys per block (2 stages of 32)
#define KSTG 32
#define NSG (SK / KTOT)        // 16 stored split groups
#define NTILE (SQ / QPB)       // 16
#define TPB 128
#define NTAIL 4

#define LOG2E 1.4426950408889634f
#define ABS2_MASK 0x7FFFFFFF7FFFFFFFULL

typedef unsigned long long ull;

// partials: [b][sg(16)][dp(32)][q(1024)]  (8MB, L2-resident)
__device__ ull   g_pacc[(size_t)BB * NSG * (DV / 2) * SQ];
__device__ float g_pl[(size_t)BB * NSG * SQ];
__device__ int   g_cnt[BB * NTILE];
__device__ int   g_fin[BB * NTILE];

__device__ __forceinline__ ull add_f32x2(ull a, ull b) {
    ull r;
    asm("add.rn.f32x2 %0, %1, %2;" : "=l"(r) : "l"(a), "l"(b));
    return r;
}
__device__ __forceinline__ ull fma_f32x2(ull a, ull b, ull c) {
    ull r;
    asm("fma.rn.f32x2 %0, %1, %2, %3;" : "=l"(r) : "l"(a), "l"(b), "l"(c));
    return r;
}
__device__ __forceinline__ ull pack_dup(float p) {
    ull r;
    asm("mov.b64 %0, {%1, %1};" : "=l"(r) : "r"(__float_as_uint(p)));
    return r;
}
__device__ __forceinline__ ull pack2(float x, float y) {
    ull r;
    asm("mov.b64 %0, {%1, %2};" : "=l"(r) : "r"(__float_as_uint(x)), "r"(__float_as_uint(y)));
    return r;
}
__device__ __forceinline__ float ex2(float x) {
    float r;
    asm("ex2.approx.f32 %0, %1;" : "=f"(r) : "f"(x));
    return r;
}
__device__ __forceinline__ float hadd(ull a) {
    float2 f = *(float2*)&a;
    return f.x + f.y;
}

__global__ __launch_bounds__(TPB, 5)
void attn_fused(const float* __restrict__ q, const float* __restrict__ k,
                const float* __restrict__ v, const int* __restrict__ mask,
                float* __restrict__ out)
{
    const int b   = blockIdx.z;
    const int sg  = blockIdx.y;            // split group 0..15 (64 keys)
    const int qt  = blockIdx.x;            // q tile 0..15
    const int tid = threadIdx.x;
    const int qc  = tid & 15;              // q column: queries 4qc..4qc+3
    const int kr  = tid >> 4;              // k row (phase1): keys 4kr..4kr+3
    const int dvc = kr;                    // dv column (phase2): dp 4dvc..4dvc+3
    const int qc4 = 4 * qc;
    const int kr4 = 4 * kr;

    // smem: Q tile (packed dim-pairs x query), K stage (negated, transposed),
    // V stage, score tile, reduction buffers.
    __shared__ __align__(16) ull   qs[DD / 2][QPB];      // 16KB
    __shared__ __align__(16) ull   ks[DD / 2][KSTG];     // 8KB
    __shared__ __align__(16) ull   vs[KSTG][DV / 2];     // 8KB
    __shared__ __align__(16) float ps[KSTG][QPB];        // 8KB
    __shared__ __align__(16) ull   k0p[DD / 2];
    __shared__ float bias[KSTG];
    __shared__ float lbuf[8][QPB];
    __shared__ float d0s[QPB];
    __shared__ int   rank_s;

    // ---- one-time loads: Q tile (transposed+packed), negated k0 row ----
    {
        const float* qb = q + ((size_t)b * SQ + qt * QPB) * DD;
#pragma unroll
        for (int idx = tid; idx < QPB * 16; idx += TPB) {
            int qq = idx >> 4, f = idx & 15;
            float4 t = ((const float4*)(qb + (size_t)qq * DD))[f];
            qs[2 * f][qq]     = pack2(t.x, t.y);
            qs[2 * f + 1][qq] = pack2(t.z, t.w);
        }
        if (tid < 16) {
            float4 t = ((const float4*)(k + (size_t)b * SK * DD))[tid];
            k0p[2 * tid]     = pack2(-t.x, -t.y);
            k0p[2 * tid + 1] = pack2(-t.z, -t.w);
        }
    }
    __syncthreads();

    // ---- reference distances d0 (16 threads, 4 queries each) ----
    if (tid < 16) {
        ull D[4] = {0ULL, 0ULL, 0ULL, 0ULL};
#pragma unroll 4
        for (int dp = 0; dp < DD / 2; dp++) {
            ull k0 = k0p[dp];
#pragma unroll
            for (int a = 0; a < 4; a++)
                D[a] = add_f32x2(D[a], add_f32x2(qs[dp][4 * tid + a], k0) & ABS2_MASK);
        }
#pragma unroll
        for (int a = 0; a < 4; a++)
            d0s[4 * tid + a] = hadd(D[a]) * LOG2E;
    }
    __syncthreads();

    float d0l2[4];
#pragma unroll
    for (int a = 0; a < 4; a++) d0l2[a] = d0s[qc4 + a];

    ull acc[4][4];                 // [q][dvpair] accumulators, persist 2 stages
#pragma unroll
    for (int a = 0; a < 4; a++)
#pragma unroll
        for (int i = 0; i < 4; i++) acc[a][i] = 0ULL;
    float lt = 0.0f;               // denominator (threads 0..63 own query tid)

#pragma unroll 1
    for (int st = 0; st < 2; st++) {
        const int kbase = sg * KTOT + st * KSTG;
        if (st) __syncthreads();   // prev stage phase2 done with ks/vs/ps

        // stage loads: K (negated, transposed, packed), V, mask bias
        {
            const float* kb = k + ((size_t)b * SK + kbase) * DD;
#pragma unroll
            for (int idx = tid; idx < KSTG * 16; idx += TPB) {
                int kk = idx >> 4, f = idx & 15;
                float4 t = ((const float4*)(kb + (size_t)kk * DD))[f];
                ks[2 * f][kk]     = pack2(-t.x, -t.y);
                ks[2 * f + 1][kk] = pack2(-t.z, -t.w);
            }
            const float4* vb = (const float4*)(v + ((size_t)b * SK + kbase) * DV);
#pragma unroll
            for (int idx = tid; idx < KSTG * DV / 4; idx += TPB)
                ((float4*)&vs[0][0])[idx] = vb[idx];
            if (tid < KSTG)
                bias[tid] = mask[(size_t)b * SK + kbase + tid] ? 0.0f : 1e9f;
        }
        __syncthreads();

        // ---- phase 1: distance GEMM, thread tile 4q x 4k ----
        ull S[16];
#pragma unroll
        for (int i = 0; i < 16; i++) S[i] = 0ULL;
#pragma unroll 4
        for (int dp = 0; dp < DD / 2; dp++) {
            ulonglong2 qa = *(const ulonglong2*)&qs[dp][qc4];
            ulonglong2 qb2 = *(const ulonglong2*)&qs[dp][qc4 + 2];
            ulonglong2 ka = *(const ulonglong2*)&ks[dp][kr4];
            ulonglong2 kb2 = *(const ulonglong2*)&ks[dp][kr4 + 2];
            ull qv[4] = {qa.x, qa.y, qb2.x, qb2.y};
            ull kv[4] = {ka.x, ka.y, kb2.x, kb2.y};
#pragma unroll
            for (int a = 0; a < 4; a++)
#pragma unroll
                for (int bb2 = 0; bb2 < 4; bb2++)
                    S[4 * a + bb2] =
                        add_f32x2(S[4 * a + bb2],
                                  add_f32x2(qv[a], kv[bb2]) & ABS2_MASK);
        }

        // ---- phase 1b: softmax numerators -> ps, partial sums -> lbuf ----
#pragma unroll
        for (int a = 0; a < 4; a++) {
            float lp = 0.0f;
#pragma unroll
            for (int bb2 = 0; bb2 < 4; bb2++) {
                float dist = hadd(S[4 * a + bb2]);
                float p = ex2(fmaf(dist + bias[kr4 + bb2], -LOG2E, d0l2[a]));
                lp += p;
                ps[kr4 + bb2][qc4 + a] = p;
            }
            lbuf[kr][qc4 + a] = lp;
        }
        __syncthreads();

        // ---- phase 2: AV GEMM, thread tile 4q x 8dv ----
#pragma unroll 4
        for (int j = 0; j < KSTG; j++) {
            float4 p4 = *(const float4*)&ps[j][qc4];
            ulonglong2 va = *(const ulonglong2*)&vs[j][4 * dvc];
            ulonglong2 vb2 = *(const ulonglong2*)&vs[j][4 * dvc + 2];
            ull v0 = va.x, v1 = va.y, v2 = vb2.x, v3 = vb2.y;
            const float* pf = (const float*)&p4;
#pragma unroll
            for (int a = 0; a < 4; a++) {
                ull pp = pack_dup(pf[a]);
                acc[a][0] = fma_f32x2(v0, pp, acc[a][0]);
                acc[a][1] = fma_f32x2(v1, pp, acc[a][1]);
                acc[a][2] = fma_f32x2(v2, pp, acc[a][2]);
                acc[a][3] = fma_f32x2(v3, pp, acc[a][3]);
            }
        }

        // denominator accumulation (threads 0..63, query = tid)
        if (tid < QPB) {
#pragma unroll
            for (int r = 0; r < 8; r++) lt += lbuf[r][tid];
        }
    }

    // ---- store partials ----
    {
        ull* pb = g_pacc + ((size_t)(b * NSG + sg) * (DV / 2)) * SQ;
#pragma unroll
        for (int a = 0; a < 4; a++)
#pragma unroll
            for (int i = 0; i < 4; i++)
                pb[(size_t)(4 * dvc + i) * SQ + qt * QPB + qc4 + a] = acc[a][i];
        if (tid < QPB)
            g_pl[(size_t)(b * NSG + sg) * SQ + qt * QPB + tid] = lt;
    }

    // ---- arrival ticket: last NTAIL blocks per (b, qtile) combine ----
    const int tile = b * NTILE + qt;
    __threadfence();
    __syncthreads();
    if (tid == 0) rank_s = atomicAdd(&g_cnt[tile], 1);
    __syncthreads();
    const int rk = rank_s;
    if (rk < NSG - NTAIL) return;

    if (tid == 0) {
        while (*(volatile int*)&g_cnt[tile] < NSG) { }
    }
    __syncthreads();
    __threadfence();

    const int r   = rk - (NSG - NTAIL);     // 0..3 -> dp slice [8r, 8r+8)
    const int ql  = tid & 63;
    const int dh  = tid >> 6;               // 0..1
    const int qi  = qt * QPB + ql;
    const int dpb = 8 * r + 4 * dh;         // 4 dp per thread

    float ltt = 0.0f;
#pragma unroll
    for (int s2 = 0; s2 < NSG; s2++)
        ltt += g_pl[(size_t)(b * NSG + s2) * SQ + qi];
    const float li = 1.0f / ltt;

    ull a2[4] = {0ULL, 0ULL, 0ULL, 0ULL};
#pragma unroll
    for (int s2 = 0; s2 < NSG; s2++) {
        const ull* base =
            g_pacc + ((size_t)(b * NSG + s2) * (DV / 2) + dpb) * SQ + qi;
#pragma unroll
        for (int i = 0; i < 4; i++)
            a2[i] = add_f32x2(a2[i], base[(size_t)i * SQ]);
    }
#pragma unroll
    for (int i = 0; i < 4; i++) {
        float2 f = *(float2*)&a2[i];
        float2 rr = make_float2(f.x * li, f.y * li);
        *(float2*)&out[((size_t)b * SQ + qi) * DV + 2 * (dpb + i)] = rr;
    }

    __threadfence();
    __syncthreads();
    if (tid == 0) {
        int f = atomicAdd(&g_fin[tile], 1);
        if (f == NTAIL - 1) {
            g_cnt[tile] = 0;
            g_fin[tile] = 0;
            __threadfence();
        }
    }
}

extern "C" void kernel_launch(void* const* d_in, const int* in_sizes, int n_in,
                              void* d_out, int out_size)
{
    const float* q    = (const float*)d_in[0];
    const float* k    = (const float*)d_in[1];
    const float* v    = (const float*)d_in[2];
    const int*   mask = (const int*)d_in[3];
    float* out = (float*)d_out;

    dim3 grid(NTILE, NSG, BB);
    attn_fused<<<grid, TPB>>>(q, k, v, mask, out);
}

// round 9
// speedup vs baseline: 1.3054x; 1.3054x over previous
#include <cuda_runtime.h>
#include <cstdint>

#define BB 2
#define SQ 1024
#define SK 1024
#define DD 64
#define DV 64
#define NSPLIT 32
#define KSMAX 32               // max compacted keys per split (1024/32)
#define QPB 32                 // queries per block (2 warps x 16)
#define TPB 64
#define NTILE (SQ / QPB)       // 32
#define NTAIL 4

#define LOG2E 1.4426950408889634f
#define ABS2_MASK 0x7FFFFFFF7FFFFFFFULL
#define FULLM 0xffffffffu

typedef unsigned long long ull;

// compacted K/V (unmasked keys only) + counts
__device__ float g_kc[(size_t)BB * SK * DD];
__device__ float g_vc[(size_t)BB * SK * DV];
__device__ int   g_nc[BB];

// partials: [b][split(32)][dp(32)][q(1024)]  (16MB, L2-resident)
__device__ ull   g_pacc[(size_t)BB * NSPLIT * (DV / 2) * SQ];
__device__ float g_pl[(size_t)BB * NSPLIT * SQ];
__device__ int   g_cnt[BB * NTILE];
__device__ int   g_fin[BB * NTILE];

__device__ __forceinline__ ull add_f32x2(ull a, ull b) {
    ull r;
    asm("add.rn.f32x2 %0, %1, %2;" : "=l"(r) : "l"(a), "l"(b));
    return r;
}
__device__ __forceinline__ ull fma_f32x2(ull a, ull b, ull c) {
    ull r;
    asm("fma.rn.f32x2 %0, %1, %2, %3;" : "=l"(r) : "l"(a), "l"(b), "l"(c));
    return r;
}
__device__ __forceinline__ ull pack_dup(float p) {
    ull r;
    asm("mov.b64 %0, {%1, %1};" : "=l"(r) : "r"(__float_as_uint(p)));
    return r;
}
__device__ __forceinline__ float ex2(float x) {
    float r;
    asm("ex2.approx.f32 %0, %1;" : "=f"(r) : "f"(x));
    return r;
}

// ---- prep: deterministic compaction of unmasked keys ----
__global__ __launch_bounds__(1024)
void compact_kv(const float* __restrict__ k, const float* __restrict__ v,
                const int* __restrict__ mask)
{
    const int b  = blockIdx.x;
    const int tid = threadIdx.x;
    const int ln = tid & 31;
    const int wd = tid >> 5;

    __shared__ int wsum[32];
    __shared__ int inv[SK];
    __shared__ int nc_s;

    int m = mask[(size_t)b * SK + tid] ? 1 : 0;
    int ws = m;
#pragma unroll
    for (int off = 1; off < 32; off <<= 1) {
        int t = __shfl_up_sync(FULLM, ws, off);
        if (ln >= off) ws += t;
    }
    if (ln == 31) wsum[wd] = ws;
    __syncthreads();
    if (tid < 32) {
        int v2 = wsum[tid], s2 = v2;
#pragma unroll
        for (int off = 1; off < 32; off <<= 1) {
            int t = __shfl_up_sync(FULLM, s2, off);
            if (tid >= off) s2 += t;
        }
        wsum[tid] = s2 - v2;           // exclusive warp offset
        if (tid == 31) nc_s = s2;      // total unmasked
    }
    __syncthreads();
    int incl = ws + wsum[wd];
    if (m) inv[incl - 1] = tid;
    if (tid == 0) g_nc[b] = nc_s;
    __syncthreads();

    // gather: one warp per compacted row, 32 lanes x float2
    const int nc = nc_s;
    for (int r = wd; r < nc; r += 32) {
        int src = inv[r];
        float2 kk = ((const float2*)(k + ((size_t)b * SK + src) * DD))[ln];
        ((float2*)(g_kc + ((size_t)b * SK + r) * DD))[ln] = kk;
        float2 vv = ((const float2*)(v + ((size_t)b * SK + src) * DV))[ln];
        ((float2*)(g_vc + ((size_t)b * SK + r) * DV))[ln] = vv;
    }
}

// L1 distance over 32 dims: 8 LDS.128 (2 distinct addrs/warp), 16 packed
// diffs + abs, 4 accumulation chains.
__device__ __forceinline__ float l1_32(const ulonglong2* __restrict__ kp,
                                       const ull* __restrict__ qn)
{
    ulonglong2 ka = kp[0];
    ulonglong2 kb = kp[1];
    ull s0 = add_f32x2(ka.x, qn[0]) & ABS2_MASK;
    ull s1 = add_f32x2(ka.y, qn[1]) & ABS2_MASK;
    ull s2 = add_f32x2(kb.x, qn[2]) & ABS2_MASK;
    ull s3 = add_f32x2(kb.y, qn[3]) & ABS2_MASK;
#pragma unroll
    for (int i = 2; i < 8; i += 2) {
        ulonglong2 kc = kp[i];
        ulonglong2 kd = kp[i + 1];
        s0 = add_f32x2(s0, add_f32x2(kc.x, qn[2 * i])     & ABS2_MASK);
        s1 = add_f32x2(s1, add_f32x2(kc.y, qn[2 * i + 1]) & ABS2_MASK);
        s2 = add_f32x2(s2, add_f32x2(kd.x, qn[2 * i + 2]) & ABS2_MASK);
        s3 = add_f32x2(s3, add_f32x2(kd.y, qn[2 * i + 3]) & ABS2_MASK);
    }
    s0 = add_f32x2(s0, s2);
    s1 = add_f32x2(s1, s3);
    s0 = add_f32x2(s0, s1);
    float2 f = *(float2*)&s0;
    return f.x + f.y;
}

__global__ __launch_bounds__(TPB, 8)
void attn_main(const float* __restrict__ q, const float* __restrict__ korig,
               float* __restrict__ out)
{
    const int b   = blockIdx.z;
    const int sg  = blockIdx.y;            // split 0..31 of the compacted list
    const int qt  = blockIdx.x;            // q tile 0..31
    const int tid = threadIdx.x;
    const int wid = tid >> 5;
    const int ln  = tid & 31;
    const int s   = ln & 15;               // query slot
    const int h   = ln >> 4;               // dim half -> dims [32h, 32h+32)
    const int qi  = qt * QPB + wid * 16 + s;

    __shared__ __align__(16) float ks[KSMAX][DD];   // 8KB
    __shared__ __align__(16) float vs[KSMAX][DV];   // 8KB
    __shared__ __align__(16) float k0s[DD];
    __shared__ int rank_s;

    const int nc    = g_nc[b];
    const int start = (nc * sg) / NSPLIT;
    const int cnt   = (nc * (sg + 1)) / NSPLIT - start;   // <= 32

    // cooperative stage load: cnt compacted keys of K and V (single stage)
    {
        const float4* kb4 = (const float4*)(g_kc + ((size_t)b * SK + start) * DD);
        const float4* vb4 = (const float4*)(g_vc + ((size_t)b * SK + start) * DV);
        for (int i = tid; i < cnt * 16; i += TPB) {
            ((float4*)&ks[0][0])[i] = kb4[i];
            ((float4*)&vs[0][0])[i] = vb4[i];
        }
        if (tid < DD / 4)
            ((float4*)k0s)[tid] = ((const float4*)(korig + (size_t)b * SK * DD))[tid];
    }

    // this thread's negated q half, packed f32x2: 16 ull
    ull qn[16];
    {
        const float* qrow = q + ((size_t)b * SQ + qi) * DD + 32 * h;
#pragma unroll
        for (int i = 0; i < 8; i++) {
            float4 t = ((const float4*)qrow)[i];
            float2 a = make_float2(-t.x, -t.y);
            float2 d = make_float2(-t.z, -t.w);
            qn[2 * i]     = *(ull*)&a;
            qn[2 * i + 1] = *(ull*)&d;
        }
    }
    __syncthreads();

    // reference distance vs original k[b][0] (shared across all splits)
    float d0l2;
    {
        float dh = l1_32((const ulonglong2*)(k0s + 32 * h), qn);
        dh += __shfl_xor_sync(FULLM, dh, 16);
        d0l2 = dh * LOG2E;
    }

    ull acc[16];
#pragma unroll
    for (int i = 0; i < 16; i++) acc[i] = 0ULL;
    float lsum = 0.0f;

#pragma unroll 2
    for (int j = 0; j < cnt; j++) {
        float dh = l1_32((const ulonglong2*)(&ks[j][32 * h]), qn);
        dh += __shfl_xor_sync(FULLM, dh, 16);
        float p = ex2(fmaf(dh, -LOG2E, d0l2));       // exp(dist0 - dist), no bias
        lsum += p;
        ull pp = pack_dup(p);

        const ulonglong2* vp = (const ulonglong2*)(&vs[j][32 * h]);
#pragma unroll
        for (int i = 0; i < 8; i++) {
            ulonglong2 vv = vp[i];
            acc[2 * i]     = fma_f32x2(vv.x, pp, acc[2 * i]);
            acc[2 * i + 1] = fma_f32x2(vv.y, pp, acc[2 * i + 1]);
        }
    }

    // store partials: dp = 16h + i (16-lane coalesced runs)
    {
        ull* pb = g_pacc + ((size_t)(b * NSPLIT + sg) * (DV / 2)) * SQ;
#pragma unroll
        for (int i = 0; i < 16; i++)
            pb[(size_t)(16 * h + i) * SQ + qi] = acc[i];
        if (h == 0)
            g_pl[(size_t)(b * NSPLIT + sg) * SQ + qi] = lsum;
    }

    // ---- arrival ticket: last NTAIL blocks per (b, qtile) combine ----
    const int tile = b * NTILE + qt;
    __threadfence();
    __syncthreads();
    if (tid == 0) rank_s = atomicAdd(&g_cnt[tile], 1);
    __syncthreads();
    const int rk = rank_s;
    if (rk < NSPLIT - NTAIL) return;

    if (tid == 0) {
        while (*(volatile int*)&g_cnt[tile] < NSPLIT) { }
    }
    __syncthreads();
    __threadfence();

    const int r   = rk - (NSPLIT - NTAIL);   // 0..3 -> dp slice [8r, 8r+8)
    const int ql  = tid & 31;
    const int dh2 = tid >> 5;                // 0..1
    const int qi2 = qt * QPB + ql;
    const int dpb = 8 * r + 4 * dh2;         // 4 dp per thread

    float lt = 0.0f;
#pragma unroll
    for (int s2 = 0; s2 < NSPLIT; s2++)
        lt += g_pl[(size_t)(b * NSPLIT + s2) * SQ + qi2];
    const float li = 1.0f / lt;

    ull a2[4] = {0ULL, 0ULL, 0ULL, 0ULL};
#pragma unroll
    for (int s2 = 0; s2 < NSPLIT; s2++) {
        const ull* base =
            g_pacc + ((size_t)(b * NSPLIT + s2) * (DV / 2) + dpb) * SQ + qi2;
#pragma unroll
        for (int i = 0; i < 4; i++)
            a2[i] = add_f32x2(a2[i], base[(size_t)i * SQ]);
    }
#pragma unroll
    for (int i = 0; i < 4; i++) {
        float2 f = *(float2*)&a2[i];
        float2 rr = make_float2(f.x * li, f.y * li);
        *(float2*)&out[((size_t)b * SQ + qi2) * DV + 2 * (dpb + i)] = rr;
    }

    __threadfence();
    __syncthreads();
    if (tid == 0) {
        int f = atomicAdd(&g_fin[tile], 1);
        if (f == NTAIL - 1) {
            g_cnt[tile] = 0;
            g_fin[tile] = 0;
            __threadfence();
        }
    }
}

extern "C" void kernel_launch(void* const* d_in, const int* in_sizes, int n_in,
                              void* d_out, int out_size)
{
    const float* q    = (const float*)d_in[0];
    const float* k    = (const float*)d_in[1];
    const float* v    = (const float*)d_in[2];
    const int*   mask = (const int*)d_in[3];
    float* out = (float*)d_out;

    compact_kv<<<BB, 1024>>>(k, v, mask);

    dim3 grid(NTILE, NSPLIT, BB);
    attn_main<<<grid, TPB>>>(q, k, out);
}

// round 10
// speedup vs baseline: 1.3725x; 1.0514x over previous
#include <cuda_runtime.h>
#include <cstdint>

#define BB 2
#define SQ 1024
#define SK 1024
#define DD 64
#define DV 64
#define NSPLIT 32
#define KSMAX 32               // max compacted keys per split
#define QPB 64                 // queries per block (2 warps x 32)
#define TPB 64
#define NTILE (SQ / QPB)       // 16
#define NTAIL 8

#define LOG2E 1.4426950408889634f
#define ABS2_MASK 0x7FFFFFFF7FFFFFFFULL
#define FULLM 0xffffffffu

typedef unsigned long long ull;

__device__ int g_inv[BB * SK];   // compacted index -> original key row
__device__ int g_nc[BB];

// partials: [b][split(32)][dp(32)][q(1024)]  (16MB, L2-resident)
__device__ ull   g_pacc[(size_t)BB * NSPLIT * (DV / 2) * SQ];
__device__ float g_pl[(size_t)BB * NSPLIT * SQ];
__device__ int   g_cnt[BB * NTILE];
__device__ int   g_fin[BB * NTILE];

__device__ __forceinline__ ull add_f32x2(ull a, ull b) {
    ull r;
    asm("add.rn.f32x2 %0, %1, %2;" : "=l"(r) : "l"(a), "l"(b));
    return r;
}
__device__ __forceinline__ ull fma_f32x2(ull a, ull b, ull c) {
    ull r;
    asm("fma.rn.f32x2 %0, %1, %2, %3;" : "=l"(r) : "l"(a), "l"(b), "l"(c));
    return r;
}
__device__ __forceinline__ ull pack_dup(float p) {
    ull r;
    asm("mov.b64 %0, {%1, %1};" : "=l"(r) : "r"(__float_as_uint(p)));
    return r;
}
__device__ __forceinline__ float ex2(float x) {
    float r;
    asm("ex2.approx.f32 %0, %1;" : "=f"(r) : "f"(x));
    return r;
}

// ---- prep: compute compaction permutation only (no data movement) ----
__global__ __launch_bounds__(1024)
void scan_mask(const int* __restrict__ mask)
{
    const int b   = blockIdx.x;
    const int tid = threadIdx.x;
    const int ln  = tid & 31;
    const int wd  = tid >> 5;

    __shared__ int wsum[32];

    int m = mask[(size_t)b * SK + tid] ? 1 : 0;
    int ws = m;
#pragma unroll
    for (int off = 1; off < 32; off <<= 1) {
        int t = __shfl_up_sync(FULLM, ws, off);
        if (ln >= off) ws += t;
    }
    if (ln == 31) wsum[wd] = ws;
    __syncthreads();
    if (tid < 32) {
        int v2 = wsum[tid], s2 = v2;
#pragma unroll
        for (int off = 1; off < 32; off <<= 1) {
            int t = __shfl_up_sync(FULLM, s2, off);
            if (tid >= off) s2 += t;
        }
        wsum[tid] = s2 - v2;            // exclusive warp offset
        if (tid == 31) g_nc[b] = s2;    // total unmasked
    }
    __syncthreads();
    int incl = ws + wsum[wd];
    if (m) g_inv[b * SK + incl - 1] = tid;
}

// dual-query L1 over 32 dims: 8 shared LDS.128, 8 accumulation chains
__device__ __forceinline__ float2 l1_32x2(const ulonglong2* __restrict__ kp,
                                          const ull* __restrict__ qa,
                                          const ull* __restrict__ qb)
{
    ulonglong2 k0 = kp[0];
    ulonglong2 k1 = kp[1];
    ull a0 = add_f32x2(k0.x, qa[0]) & ABS2_MASK;
    ull b0 = add_f32x2(k0.x, qb[0]) & ABS2_MASK;
    ull a1 = add_f32x2(k0.y, qa[1]) & ABS2_MASK;
    ull b1 = add_f32x2(k0.y, qb[1]) & ABS2_MASK;
    ull a2 = add_f32x2(k1.x, qa[2]) & ABS2_MASK;
    ull b2 = add_f32x2(k1.x, qb[2]) & ABS2_MASK;
    ull a3 = add_f32x2(k1.y, qa[3]) & ABS2_MASK;
    ull b3 = add_f32x2(k1.y, qb[3]) & ABS2_MASK;
#pragma unroll
    for (int i = 2; i < 8; i += 2) {
        ulonglong2 kc = kp[i];
        ulonglong2 kd = kp[i + 1];
        a0 = add_f32x2(a0, add_f32x2(kc.x, qa[2 * i])     & ABS2_MASK);
        b0 = add_f32x2(b0, add_f32x2(kc.x, qb[2 * i])     & ABS2_MASK);
        a1 = add_f32x2(a1, add_f32x2(kc.y, qa[2 * i + 1]) & ABS2_MASK);
        b1 = add_f32x2(b1, add_f32x2(kc.y, qb[2 * i + 1]) & ABS2_MASK);
        a2 = add_f32x2(a2, add_f32x2(kd.x, qa[2 * i + 2]) & ABS2_MASK);
        b2 = add_f32x2(b2, add_f32x2(kd.x, qb[2 * i + 2]) & ABS2_MASK);
        a3 = add_f32x2(a3, add_f32x2(kd.y, qa[2 * i + 3]) & ABS2_MASK);
        b3 = add_f32x2(b3, add_f32x2(kd.y, qb[2 * i + 3]) & ABS2_MASK);
    }
    a0 = add_f32x2(a0, a2);
    b0 = add_f32x2(b0, b2);
    a1 = add_f32x2(a1, a3);
    b1 = add_f32x2(b1, b3);
    a0 = add_f32x2(a0, a1);
    b0 = add_f32x2(b0, b1);
    float2 fa = *(float2*)&a0;
    float2 fb = *(float2*)&b0;
    return make_float2(fa.x + fa.y, fb.x + fb.y);
}

__global__ __launch_bounds__(TPB, 6)
void attn_main(const float* __restrict__ q, const float* __restrict__ k,
               const float* __restrict__ v, float* __restrict__ out)
{
    const int b   = blockIdx.z;
    const int sg  = blockIdx.y;            // split of compacted list
    const int qt  = blockIdx.x;            // q tile 0..15
    const int tid = threadIdx.x;
    const int wid = tid >> 5;              // warp 0/1 -> queries [32w, 32w+32)
    const int ln  = tid & 31;
    const int s   = ln & 15;               // query slot
    const int h   = ln >> 4;               // dim half -> dims [32h, 32h+32)
    const int qiA = qt * QPB + wid * 32 + s;        // query A
    const int qiB = qiA + 16;                       // query B

    __shared__ __align__(16) float ks[KSMAX][DD];   // 8KB
    __shared__ __align__(16) float vs[KSMAX][DV];   // 8KB
    __shared__ __align__(16) float k0s[DD];
    __shared__ int rank_s;

    const int nc    = g_nc[b];
    const int start = (nc * sg) / NSPLIT;
    const int cnt   = (nc * (sg + 1)) / NSPLIT - start;   // <= 32

    // gather stage load: warp per compacted row, direct from original K/V
    for (int j = wid; j < cnt; j += 2) {
        int src = g_inv[b * SK + start + j];
        float2 kk = ((const float2*)(k + ((size_t)b * SK + src) * DD))[ln];
        ((float2*)&ks[j][0])[ln] = kk;
        float2 vv = ((const float2*)(v + ((size_t)b * SK + src) * DV))[ln];
        ((float2*)&vs[j][0])[ln] = vv;
    }
    if (tid < DD / 4)
        ((float4*)k0s)[tid] = ((const float4*)(k + (size_t)b * SK * DD))[tid];

    // negated q halves for both queries, packed f32x2: 2 x 16 ull
    ull qnA[16], qnB[16];
    {
        const float* qra = q + ((size_t)b * SQ + qiA) * DD + 32 * h;
        const float* qrb = q + ((size_t)b * SQ + qiB) * DD + 32 * h;
#pragma unroll
        for (int i = 0; i < 8; i++) {
            float4 t = ((const float4*)qra)[i];
            float2 x = make_float2(-t.x, -t.y);
            float2 y = make_float2(-t.z, -t.w);
            qnA[2 * i]     = *(ull*)&x;
            qnA[2 * i + 1] = *(ull*)&y;
            float4 u = ((const float4*)qrb)[i];
            float2 z = make_float2(-u.x, -u.y);
            float2 w = make_float2(-u.z, -u.w);
            qnB[2 * i]     = *(ull*)&z;
            qnB[2 * i + 1] = *(ull*)&w;
        }
    }
    __syncthreads();

    // reference distances vs original k[b][0]
    float d0A, d0B;
    {
        float2 dh = l1_32x2((const ulonglong2*)(k0s + 32 * h), qnA, qnB);
        dh.x += __shfl_xor_sync(FULLM, dh.x, 16);
        dh.y += __shfl_xor_sync(FULLM, dh.y, 16);
        d0A = dh.x * LOG2E;
        d0B = dh.y * LOG2E;
    }

    ull accA[16], accB[16];
#pragma unroll
    for (int i = 0; i < 16; i++) { accA[i] = 0ULL; accB[i] = 0ULL; }
    float lsA = 0.0f, lsB = 0.0f;

#pragma unroll 2
    for (int j = 0; j < cnt; j++) {
        float2 dh = l1_32x2((const ulonglong2*)(&ks[j][32 * h]), qnA, qnB);
        dh.x += __shfl_xor_sync(FULLM, dh.x, 16);
        dh.y += __shfl_xor_sync(FULLM, dh.y, 16);
        float pA = ex2(fmaf(dh.x, -LOG2E, d0A));
        float pB = ex2(fmaf(dh.y, -LOG2E, d0B));
        lsA += pA;
        lsB += pB;
        ull ppA = pack_dup(pA);
        ull ppB = pack_dup(pB);

        const ulonglong2* vp = (const ulonglong2*)(&vs[j][32 * h]);
#pragma unroll
        for (int i = 0; i < 8; i++) {
            ulonglong2 vv = vp[i];
            accA[2 * i]     = fma_f32x2(vv.x, ppA, accA[2 * i]);
            accA[2 * i + 1] = fma_f32x2(vv.y, ppA, accA[2 * i + 1]);
            accB[2 * i]     = fma_f32x2(vv.x, ppB, accB[2 * i]);
            accB[2 * i + 1] = fma_f32x2(vv.y, ppB, accB[2 * i + 1]);
        }
    }

    // store partials: dp = 16h + i, 16-lane coalesced runs per query group
    {
        ull* pb = g_pacc + ((size_t)(b * NSPLIT + sg) * (DV / 2)) * SQ;
#pragma unroll
        for (int i = 0; i < 16; i++) {
            pb[(size_t)(16 * h + i) * SQ + qiA] = accA[i];
            pb[(size_t)(16 * h + i) * SQ + qiB] = accB[i];
        }
        if (h == 0) {
            float* pl = g_pl + (size_t)(b * NSPLIT + sg) * SQ;
            pl[qiA] = lsA;
            pl[qiB] = lsB;
        }
    }

    // ---- arrival ticket: last NTAIL blocks per (b, qtile) combine ----
    const int tile = b * NTILE + qt;
    __threadfence();
    __syncthreads();
    if (tid == 0) rank_s = atomicAdd(&g_cnt[tile], 1);
    __syncthreads();
    const int rk = rank_s;
    if (rk < NSPLIT - NTAIL) return;

    if (tid == 0) {
        while (*(volatile int*)&g_cnt[tile] < NSPLIT) { }
    }
    __syncthreads();
    __threadfence();

    const int r   = rk - (NSPLIT - NTAIL);   // 0..7 -> dp slice [4r, 4r+4)
    const int qi2 = qt * QPB + tid;          // thread = query
    const int dpb = 4 * r;

    float lt = 0.0f;
#pragma unroll
    for (int s2 = 0; s2 < NSPLIT; s2++)
        lt += g_pl[(size_t)(b * NSPLIT + s2) * SQ + qi2];
    const float li = 1.0f / lt;

    ull a2[4] = {0ULL, 0ULL, 0ULL, 0ULL};
#pragma unroll
    for (int s2 = 0; s2 < NSPLIT; s2++) {
        const ull* base =
            g_pacc + ((size_t)(b * NSPLIT + s2) * (DV / 2) + dpb) * SQ + qi2;
#pragma unroll
        for (int i = 0; i < 4; i++)
            a2[i] = add_f32x2(a2[i], base[(size_t)i * SQ]);
    }
#pragma unroll
    for (int i = 0; i < 4; i++) {
        float2 f = *(float2*)&a2[i];
        float2 rr = make_float2(f.x * li, f.y * li);
        *(float2*)&out[((size_t)b * SQ + qi2) * DV + 2 * (dpb + i)] = rr;
    }

    __threadfence();
    __syncthreads();
    if (tid == 0) {
        int f = atomicAdd(&g_fin[tile], 1);
        if (f == NTAIL - 1) {
            g_cnt[tile] = 0;
            g_fin[tile] = 0;
            __threadfence();
        }
    }
}

extern "C" void kernel_launch(void* const* d_in, const int* in_sizes, int n_in,
                              void* d_out, int out_size)
{
    const float* q    = (const float*)d_in[0];
    const float* k    = (const float*)d_in[1];
    const float* v    = (const float*)d_in[2];
    const int*   mask = (const int*)d_in[3];
    float* out = (float*)d_out;

    scan_mask<<<BB, 1024>>>(mask);

    dim3 grid(NTILE, NSPLIT, BB);
    attn_main<<<grid, TPB>>>(q, k, v, out);
}

// round 11
// speedup vs baseline: 1.4581x; 1.0624x over previous
#include <cuda_runtime.h>
#include <cstdint>

#define BB 2
#define SQ 1024
#define SK 1024
#define DD 64
#define DV 64
#define NSPLIT 16
#define KSMAX 64               // worst case: all keys unmasked
#define KB 16                  // keys per phase pass
#define QPB 64
#define TPB 128
#define NTILE (SQ / QPB)       // 16
#define NTAIL 4

#define LOG2E 1.4426950408889634f
#define ABS2_MASK 0x7FFFFFFF7FFFFFFFULL
#define FULLM 0xffffffffu

typedef unsigned long long ull;

__device__ int g_inv[BB * SK];   // compacted index -> original key row
__device__ int g_nc[BB];

// partials: [b][split(16)][dp(32)][q(1024)]  (8MB, L2-resident)
__device__ ull   g_pacc[(size_t)BB * NSPLIT * (DV / 2) * SQ];
__device__ float g_pl[(size_t)BB * NSPLIT * SQ];
__device__ int   g_cnt[BB * NTILE];
__device__ int   g_fin[BB * NTILE];

__device__ __forceinline__ ull add_f32x2(ull a, ull b) {
    ull r;
    asm("add.rn.f32x2 %0, %1, %2;" : "=l"(r) : "l"(a), "l"(b));
    return r;
}
__device__ __forceinline__ ull fma_f32x2(ull a, ull b, ull c) {
    ull r;
    asm("fma.rn.f32x2 %0, %1, %2, %3;" : "=l"(r) : "l"(a), "l"(b), "l"(c));
    return r;
}
__device__ __forceinline__ ull pack_dup(float p) {
    ull r;
    asm("mov.b64 %0, {%1, %1};" : "=l"(r) : "r"(__float_as_uint(p)));
    return r;
}
__device__ __forceinline__ float ex2(float x) {
    float r;
    asm("ex2.approx.f32 %0, %1;" : "=f"(r) : "f"(x));
    return r;
}

// ---- prep: compaction permutation (proven R9/R10) ----
__global__ __launch_bounds__(1024)
void scan_mask(const int* __restrict__ mask)
{
    const int b   = blockIdx.x;
    const int tid = threadIdx.x;
    const int ln  = tid & 31;
    const int wd  = tid >> 5;

    __shared__ int wsum[32];

    int m = mask[(size_t)b * SK + tid] ? 1 : 0;
    int ws = m;
#pragma unroll
    for (int off = 1; off < 32; off <<= 1) {
        int t = __shfl_up_sync(FULLM, ws, off);
        if (ln >= off) ws += t;
    }
    if (ln == 31) wsum[wd] = ws;
    __syncthreads();
    if (tid < 32) {
        int v2 = wsum[tid], s2 = v2;
#pragma unroll
        for (int off = 1; off < 32; off <<= 1) {
            int t = __shfl_up_sync(FULLM, s2, off);
            if (tid >= off) s2 += t;
        }
        wsum[tid] = s2 - v2;
        if (tid == 31) g_nc[b] = s2;
    }
    __syncthreads();
    int incl = ws + wsum[wd];
    if (m) g_inv[b * SK + incl - 1] = tid;
}

// L1 distance over 32 dims: 8 LDS.128, 4 accumulation chains (R4 proven)
__device__ __forceinline__ float l1_32(const ulonglong2* __restrict__ kp,
                                       const ull* __restrict__ qn)
{
    ulonglong2 ka = kp[0];
    ulonglong2 kb = kp[1];
    ull s0 = add_f32x2(ka.x, qn[0]) & ABS2_MASK;
    ull s1 = add_f32x2(ka.y, qn[1]) & ABS2_MASK;
    ull s2 = add_f32x2(kb.x, qn[2]) & ABS2_MASK;
    ull s3 = add_f32x2(kb.y, qn[3]) & ABS2_MASK;
#pragma unroll
    for (int i = 2; i < 8; i += 2) {
        ulonglong2 kc = kp[i];
        ulonglong2 kd = kp[i + 1];
        s0 = add_f32x2(s0, add_f32x2(kc.x, qn[2 * i])     & ABS2_MASK);
        s1 = add_f32x2(s1, add_f32x2(kc.y, qn[2 * i + 1]) & ABS2_MASK);
        s2 = add_f32x2(s2, add_f32x2(kd.x, qn[2 * i + 2]) & ABS2_MASK);
        s3 = add_f32x2(s3, add_f32x2(kd.y, qn[2 * i + 3]) & ABS2_MASK);
    }
    s0 = add_f32x2(s0, s2);
    s1 = add_f32x2(s1, s3);
    s0 = add_f32x2(s0, s1);
    float2 f = *(float2*)&s0;
    return f.x + f.y;
}

__global__ __launch_bounds__(TPB, 5)
void attn_main(const float* __restrict__ q, const float* __restrict__ k,
               const float* __restrict__ v, float* __restrict__ out)
{
    const int b    = blockIdx.z;
    const int sg   = blockIdx.y;          // split 0..15 of compacted list
    const int qt   = blockIdx.x;          // q tile 0..15
    const int tid  = threadIdx.x;
    const int h    = tid >> 6;            // dim half (and j-half in phase 1b)
    const int qloc = tid & 63;
    const int qi   = qt * QPB + qloc;

    __shared__ __align__(16) float ks[KSMAX][DD];         // 16KB
    __shared__ __align__(16) float vs[KSMAX][DV];         // 16KB
    __shared__ __align__(16) float hbuf[KB][2][QPB];      // 8KB
    __shared__ __align__(16) float k0s[DD];
    __shared__ float d0b[2][QPB];
    __shared__ float lb[2][QPB];
    __shared__ int   rank_s;

    const int nc    = g_nc[b];
    const int start = (nc * sg) / NSPLIT;
    const int cnt   = (nc * (sg + 1)) / NSPLIT - start;   // <= KSMAX
    const int cpad  = (cnt + KB - 1) & ~(KB - 1);

    // gather load: warp per compacted row, direct from original K/V (L2-hot)
    {
        const int wd = tid >> 5, ln = tid & 31;
        for (int j = wd; j < cnt; j += 4) {
            int src = g_inv[b * SK + start + j];
            float2 kk = ((const float2*)(k + ((size_t)b * SK + src) * DD))[ln];
            ((float2*)&ks[j][0])[ln] = kk;
            float2 vv = ((const float2*)(v + ((size_t)b * SK + src) * DV))[ln];
            ((float2*)&vs[j][0])[ln] = vv;
        }
        // zero V pad rows (avoid NaN*0 in phase 2)
        for (int j = cnt + wd; j < cpad; j += 4)
            ((float2*)&vs[j][0])[ln] = make_float2(0.0f, 0.0f);
        if (tid < DD / 4)
            ((float4*)k0s)[tid] = ((const float4*)(k + (size_t)b * SK * DD))[tid];
    }

    // this thread's negated q half (dims [32h, 32h+32)), packed f32x2
    ull qn[16];
    {
        const float* qrow = q + ((size_t)b * SQ + qi) * DD + 32 * h;
#pragma unroll
        for (int i = 0; i < 8; i++) {
            float4 t = ((const float4*)qrow)[i];
            float2 a = make_float2(-t.x, -t.y);
            float2 c = make_float2(-t.z, -t.w);
            qn[2 * i]     = *(ull*)&a;
            qn[2 * i + 1] = *(ull*)&c;
        }
    }
    __syncthreads();

    // reference point: dist0 = L1(q, k[b][0]), halves joined via smem
    d0b[h][qloc] = l1_32((const ulonglong2*)(k0s + 32 * h), qn);
    __syncthreads();
    const float d0l2 = (d0b[0][qloc] + d0b[1][qloc]) * LOG2E;

    ull acc[16];
#pragma unroll
    for (int i = 0; i < 16; i++) acc[i] = 0ULL;
    float lsum = 0.0f;

#pragma unroll 1
    for (int jb = 0; jb < cpad; jb += KB) {
        // phase 1a: half-distances for KB keys (independent iterations)
#pragma unroll
        for (int j = 0; j < KB; j++)
            if (jb + j < cnt)
                hbuf[j][h][qloc] = l1_32((const ulonglong2*)&ks[jb + j][32 * h], qn);
        __syncthreads();

        // phase 1b: join halves, softmax numerator p (0 for pad), in-place
#pragma unroll
        for (int t = 0; t < KB / 2; t++) {
            int j = h * (KB / 2) + t;
            float p = 0.0f;
            if (jb + j < cnt) {
                float d = hbuf[j][0][qloc] + hbuf[j][1][qloc];
                p = ex2(fmaf(d, -LOG2E, d0l2));
            }
            hbuf[j][0][qloc] = p;
            lsum += p;
        }
        __syncthreads();

        // phase 2: AV accumulation (independent chains)
#pragma unroll
        for (int j = 0; j < KB; j++) {
            ull pp = pack_dup(hbuf[j][0][qloc]);
            const ulonglong2* vp = (const ulonglong2*)&vs[jb + j][32 * h];
#pragma unroll
            for (int i = 0; i < 8; i++) {
                ulonglong2 vv = vp[i];
                acc[2 * i]     = fma_f32x2(vv.x, pp, acc[2 * i]);
                acc[2 * i + 1] = fma_f32x2(vv.y, pp, acc[2 * i + 1]);
            }
        }
        __syncthreads();
    }

    // store partials (coalesced STG.64) + denominators
    {
        ull* pb = g_pacc + ((size_t)(b * NSPLIT + sg) * (DV / 2)) * SQ;
#pragma unroll
        for (int i = 0; i < 16; i++)
            pb[(size_t)(h * 16 + i) * SQ + qi] = acc[i];
        lb[h][qloc] = lsum;
    }
    __syncthreads();
    if (h == 0)
        g_pl[(size_t)(b * NSPLIT + sg) * SQ + qi] = lsum + lb[1][qloc];

    // ---- arrival ticket: last NTAIL blocks per (b, qtile) combine ----
    const int tile = b * NTILE + qt;
    __threadfence();
    __syncthreads();
    if (tid == 0) rank_s = atomicAdd(&g_cnt[tile], 1);
    __syncthreads();
    const int c = rank_s;
    if (c < NSPLIT - NTAIL) return;

    if (tid == 0) {
        while (*(volatile int*)&g_cnt[tile] < NSPLIT) { }
    }
    __syncthreads();
    __threadfence();

    const int r = c - (NSPLIT - NTAIL);      // 0..3 -> dp slice [8r, 8r+8)

    float lt = 0.0f;
#pragma unroll
    for (int s2 = 0; s2 < NSPLIT; s2++)
        lt += g_pl[(size_t)(b * NSPLIT + s2) * SQ + qi];
    const float li = 1.0f / lt;

    const int dpb = r * 8 + h * 4;
    ull a[4] = {0ULL, 0ULL, 0ULL, 0ULL};
#pragma unroll
    for (int s2 = 0; s2 < NSPLIT; s2++) {
        const ull* base = g_pacc + ((size_t)(b * NSPLIT + s2) * (DV / 2)) * SQ + qi;
#pragma unroll
        for (int i = 0; i < 4; i++)
            a[i] = add_f32x2(a[i], base[(size_t)(dpb + i) * SQ]);
    }
#pragma unroll
    for (int i = 0; i < 4; i++) {
        float2 f = *(float2*)&a[i];
        float2 rr = make_float2(f.x * li, f.y * li);
        *(float2*)&out[((size_t)b * SQ + qi) * DV + 2 * (dpb + i)] = rr;
    }

    __threadfence();
    __syncthreads();
    if (tid == 0) {
        int f = atomicAdd(&g_fin[tile], 1);
        if (f == NTAIL - 1) {
            g_cnt[tile] = 0;
            g_fin[tile] = 0;
            __threadfence();
        }
    }
}

extern "C" void kernel_launch(void* const* d_in, const int* in_sizes, int n_in,
                              void* d_out, int out_size)
{
    const float* q    = (const float*)d_in[0];
    const float* k    = (const float*)d_in[1];
    const float* v    = (const float*)d_in[2];
    const int*   mask = (const int*)d_in[3];
    float* out = (float*)d_out;

    scan_mask<<<BB, 1024>>>(mask);

    dim3 grid(NTILE, NSPLIT, BB);
    attn_main<<<grid, TPB>>>(q, k, v, out);
}